// round 13
// baseline (speedup 1.0000x reference)
#include <cuda_runtime.h>
#include <cuda_bf16.h>

#define KDIM  64
#define LOG2E 1.4426950408889634f
#define LN2   0.6931471805599453f
#define TH    -1000000.0f
#define FULL  0xffffffffu

__device__ __forceinline__ float ex2f(float x){float y;asm("ex2.approx.f32 %0,%1;":"=f"(y):"f"(x));return y;}
__device__ __forceinline__ float lg2f(float x){float y;asm("lg2.approx.f32 %0,%1;":"=f"(y):"f"(x));return y;}
// pack {hi,lo} f32 -> bf16x2 (satfinite keeps everything finite)
__device__ __forceinline__ unsigned cvt_bf2(float hi, float lo){
    unsigned r;asm("cvt.rn.satfinite.bf16x2.f32 %0,%1,%2;":"=r"(r):"f"(hi),"f"(lo));return r;}
__device__ __forceinline__ float bflo(unsigned u){ return __int_as_float(u << 16); }
__device__ __forceinline__ float bfhi(unsigned u){ return __int_as_float(u & 0xFFFF0000u); }
// group-of-4 min (lanes 4g..4g+3)
__device__ __forceinline__ float grpmin(float v){
    v = fminf(v, __shfl_xor_sync(FULL, v, 1));
    v = fminf(v, __shfl_xor_sync(FULL, v, 2));
    return v;
}
// D += A*B, m16n8k16 bf16 (a1=a3=0 -> rows 8..15 of A are zero)
__device__ __forceinline__ void mmaA(float&d0,float&d1,float&d2,float&d3,
                                     unsigned a0,unsigned a2,unsigned b0,unsigned b1){
    asm("mma.sync.aligned.m16n8k16.row.col.f32.bf16.bf16.f32 "
        "{%0,%1,%2,%3},{%4,%5,%6,%7},{%8,%9},{%0,%1,%2,%3};"
        :"+f"(d0),"+f"(d1),"+f"(d2),"+f"(d3)
        :"r"(a0),"r"(0u),"r"(a2),"r"(0u),"r"(b0),"r"(b1));
}

// ONE WARP = 8 batch rows via m16n8k16 mma.sync. Group g (lanes 4g..4g+3) owns row g.
// State e_j (bf16) lives in A fragments a0[kt],a2[kt] (row g). The all-to-all
// s = e x E runs inside the tensor core: no smem, no barriers, no shuffled state.
// Feedback identity (validated by R12's log_norm being correct): D tile nt=2kt ->
// a0[kt], nt=2kt+1 -> a2[kt], same lane.
// Step: q = pack_bf16(D * 2^(emit*lg2e)); a = (m ? q : a_old) - d*0x00800080
// (packed exponent subtract = exact *2^-d on both halves); C2i += d;
// d = exp-field of state 0 (lane 4g a0[0].lo), broadcast by one shfl.
// Steps t >= N run masked (m=0): pure frame shift, result invariant.
__global__ __launch_bounds__(32, 1) void crf_mma_kernel(
    const float* __restrict__ y_pred,   // [B, N, K]
    const float* __restrict__ trans,    // [K, K]
    const int*   __restrict__ y_true,   // [B, N]
    float*       __restrict__ out,      // [B]
    int N, int B)
{
    const int lane = threadIdx.x & 31;
    const int g    = lane >> 2;
    const int tid  = lane & 3;
    const int rraw = blockIdx.x * 8 + g;
    const int row  = (rraw < B) ? rraw : (B - 1);

    const float* Y  = y_pred + (size_t)row * N * KDIM;
    const int*   Tr = y_true + (size_t)row * N;

    // ---- B fragments: E = exp(trans), tile (kt,nt): col j = 8nt+g ----
    unsigned Bf0[4][8], Bf1[4][8];
#pragma unroll
    for (int kt = 0; kt < 4; ++kt)
#pragma unroll
        for (int nt = 0; nt < 8; ++nt) {
            int c = 8 * nt + g, r0 = 16 * kt + 2 * tid;
            Bf0[kt][nt] = cvt_bf2(__expf(trans[(r0 + 1) * KDIM + c]),
                                  __expf(trans[(r0    ) * KDIM + c]));
            Bf1[kt][nt] = cvt_bf2(__expf(trans[(r0 + 9) * KDIM + c]),
                                  __expf(trans[(r0 + 8) * KDIM + c]));
        }

    // ---- t = 0: state init ----
    float2 e0[8];
#pragma unroll
    for (int nt = 0; nt < 8; ++nt) e0[nt] = *(const float2*)(Y + 8 * nt + 2 * tid);
    float mn0 = fminf(e0[0].x, e0[0].y);
#pragma unroll
    for (int nt = 1; nt < 8; ++nt) mn0 = fminf(mn0, fminf(e0[nt].x, e0[nt].y));
    float fm0 = (grpmin(mn0) > TH) ? 1.0f : 0.0f;

    unsigned a0[4], a2[4];
#pragma unroll
    for (int kt = 0; kt < 4; ++kt) {
        float2 qe = e0[2 * kt], qo = e0[2 * kt + 1];
        a0[kt] = cvt_bf2(ex2f(qe.y * fm0 * LOG2E), ex2f(qe.x * fm0 * LOG2E));
        a2[kt] = cvt_bf2(ex2f(qo.y * fm0 * LOG2E), ex2f(qo.x * fm0 * LOG2E));
    }
    int d = __shfl_sync(FULL, (int)((a0[0] >> 7) & 0xFFu) - 127, lane & ~3);
    int C2i = 0;

    int yt0 = Tr[0];
    float point = Y[yt0] * fm0;
    float tv = 0.0f, fmprev = fm0;

    // ---- prime pipelines ----
    float2 ring[4][8];                       // emits for step t at slot t&3
#pragma unroll
    for (int p = 1; p <= 4; ++p) {
        int tt = (p < N) ? p : (N - 1);
#pragma unroll
        for (int nt = 0; nt < 8; ++nt)
            ring[p & 3][nt] = *(const float2*)(Y + (size_t)tt * KDIM + 8 * nt + 2 * tid);
    }
    unsigned mcur;
    {
        float mn = fminf(ring[1][0].x, ring[1][0].y);
#pragma unroll
        for (int nt = 1; nt < 8; ++nt) mn = fminf(mn, fminf(ring[1][nt].x, ring[1][nt].y));
        mcur = (grpmin(mn) > TH) && (1 < N);
    }
    // label pipeline at loop entry T = 1:
    //   ytA = yt(T), ytB = yt(T+1), ytC = yt(T+2), ytD = yt(T+3)
    int ytA = Tr[(1 < N) ? 1 : (N - 1)];
    int ytB = Tr[(2 < N) ? 2 : (N - 1)];
    int ytC = Tr[(3 < N) ? 3 : (N - 1)];
    int ytD = Tr[(4 < N) ? 4 : (N - 1)];
    float pgc = Y[(size_t)((1 < N) ? 1 : (N - 1)) * KDIM + ytA];   // Y[T][yt(T)]
    float pgn = Y[(size_t)((2 < N) ? 2 : (N - 1)) * KDIM + ytB];   // Y[T+1][yt(T+1)]
    float trvc = trans[yt0 * KDIM + ytA];     // trans[yt(T-1), yt(T)]
    float trvn = trans[ytA * KDIM + ytB];     // trans[yt(T), yt(T+1)]

#define STEP(T, S, SN)                                                               \
    {                                                                                \
        float2 ev[8];                                                                \
        _Pragma("unroll")                                                            \
        for (int nt = 0; nt < 8; ++nt) ev[nt] = ring[S][nt];                         \
        int tl = ((T) + 4 < N) ? ((T) + 4) : (N - 1);                                \
        _Pragma("unroll")                                                            \
        for (int nt = 0; nt < 8; ++nt)                                               \
            ring[S][nt] = *(const float2*)(Y + (size_t)tl * KDIM + 8 * nt + 2 * tid);\
        float mn = fminf(ring[SN][0].x, ring[SN][0].y);                              \
        _Pragma("unroll")                                                            \
        for (int nt = 1; nt < 8; ++nt)                                               \
            mn = fminf(mn, fminf(ring[SN][nt].x, ring[SN][nt].y));                   \
        unsigned mnext = (grpmin(mn) > TH) && ((T) + 1 < N);                         \
        int ytL = Tr[tl];                                                            \
        /* prefetch for step T+2: Y[T+2][yt(T+2)] and trans[yt(T+1), yt(T+2)] */     \
        float pgN = Y[(size_t)(((T) + 2 < N) ? ((T) + 2) : (N - 1)) * KDIM + ytC];   \
        float trN = trans[ytB * KDIM + ytC];                                         \
        float pa[8], pb[8];                                                          \
        _Pragma("unroll")                                                            \
        for (int nt = 0; nt < 8; ++nt) {                                             \
            pa[nt] = ex2f(ev[nt].x * LOG2E);                                         \
            pb[nt] = ex2f(ev[nt].y * LOG2E);                                         \
        }                                                                            \
        float d0[8], d1[8], d2[8], d3[8];                                            \
        _Pragma("unroll")                                                            \
        for (int nt = 0; nt < 8; ++nt) {                                             \
            d0[nt] = 0.0f; d1[nt] = 0.0f; d2[nt] = 0.0f; d3[nt] = 0.0f;              \
            mmaA(d0[nt], d1[nt], d2[nt], d3[nt], a0[0], a2[0], Bf0[0][nt], Bf1[0][nt]); \
            mmaA(d0[nt], d1[nt], d2[nt], d3[nt], a0[1], a2[1], Bf0[1][nt], Bf1[1][nt]); \
            mmaA(d0[nt], d1[nt], d2[nt], d3[nt], a0[2], a2[2], Bf0[2][nt], Bf1[2][nt]); \
            mmaA(d0[nt], d1[nt], d2[nt], d3[nt], a0[3], a2[3], Bf0[3][nt], Bf1[3][nt]); \
        }                                                                            \
        unsigned dd2 = (unsigned)(d * 0x00800080);                                   \
        unsigned res[8];                                                             \
        _Pragma("unroll")                                                            \
        for (int nt = 0; nt < 8; ++nt) {                                             \
            unsigned pk = cvt_bf2(d1[nt] * pb[nt], d0[nt] * pa[nt]);                 \
            unsigned old = (nt & 1) ? a2[nt >> 1] : a0[nt >> 1];                     \
            res[nt] = (mcur ? pk : old) - dd2;                                       \
        }                                                                            \
        _Pragma("unroll")                                                            \
        for (int kt = 0; kt < 4; ++kt) { a0[kt] = res[2 * kt]; a2[kt] = res[2 * kt + 1]; } \
        C2i += d;                                                                    \
        d = __shfl_sync(FULL, (int)((a0[0] >> 7) & 0xFFu) - 127, lane & ~3);         \
        float fmc = mcur ? 1.0f : 0.0f;                                              \
        point += pgc * fmc;                                                          \
        tv += trvc * (fmprev * fmc);                                                 \
        fmprev = fmc; mcur = mnext;                                                  \
        pgc = pgn; pgn = pgN;                                                        \
        trvc = trvn; trvn = trN;                                                     \
        ytA = ytB; ytB = ytC; ytC = ytD; ytD = ytL;                                  \
    }

    // ---- main loop: t0 === 1 (mod 4); steps t >= N run masked (harmless) ----
    for (int t0 = 1; t0 < N; t0 += 4) {
        STEP(t0 + 0, 1, 2)
        STEP(t0 + 1, 2, 3)
        STEP(t0 + 2, 3, 0)
        STEP(t0 + 3, 0, 1)
    }
#undef STEP

    // ---- epilogue: se = sum_j e_j over my row; alpha2 = C2i + lg2 ----
    float se = 0.0f;
#pragma unroll
    for (int kt = 0; kt < 4; ++kt)
        se += bflo(a0[kt]) + bfhi(a0[kt]) + bflo(a2[kt]) + bfhi(a2[kt]);
    se += __shfl_xor_sync(FULL, se, 1);
    se += __shfl_xor_sync(FULL, se, 2);
    if (tid == 0 && rraw < B)
        out[rraw] = LN2 * ((float)C2i + lg2f(se)) - (point + tv);
}

extern "C" void kernel_launch(void* const* d_in, const int* in_sizes, int n_in,
                              void* d_out, int out_size) {
    const float* y_pred = (const float*)d_in[0];   // [B, N, K] f32
    const float* trans  = (const float*)d_in[1];   // [K, K]    f32
    const int*   y_true = (const int*)  d_in[2];   // [B, N]    i32
    float* out = (float*)d_out;                    // [B]       f32

    int B = out_size;                  // 512
    int N = in_sizes[2] / B;           // 1024
    int blocks = (B + 7) / 8;          // 64 warps, 8 rows each
    crf_mma_kernel<<<blocks, 32>>>(y_pred, trans, y_true, out, N, B);
}

// round 14
// speedup vs baseline: 1.0892x; 1.0892x over previous
#include <cuda_runtime.h>
#include <cuda_bf16.h>

#define KDIM  64
#define LOG2E 1.4426950408889634f
#define LN2   0.6931471805599453f
#define TH    -1000000.0f
#define FULL  0xffffffffu

__device__ __forceinline__ float ex2f(float x){float y;asm("ex2.approx.f32 %0,%1;":"=f"(y):"f"(x));return y;}
__device__ __forceinline__ float lg2f(float x){float y;asm("lg2.approx.f32 %0,%1;":"=f"(y):"f"(x));return y;}
__device__ __forceinline__ unsigned cvt_bf2(float hi, float lo){
    unsigned r;asm("cvt.rn.satfinite.bf16x2.f32 %0,%1,%2;":"=r"(r):"f"(hi),"f"(lo));return r;}
__device__ __forceinline__ float bflo(unsigned u){ return __int_as_float(u << 16); }
__device__ __forceinline__ float bfhi(unsigned u){ return __int_as_float(u & 0xFFFF0000u); }
__device__ __forceinline__ float grpmin(float v){
    v = fminf(v, __shfl_xor_sync(FULL, v, 1));
    v = fminf(v, __shfl_xor_sync(FULL, v, 2));
    return v;
}
// D = A*B + 0 (C = repeated zero reg) — kills per-step accumulator zero-MOVs
__device__ __forceinline__ void mma0(float&d0,float&d1,float&d2,float&d3,
                                     unsigned a0,unsigned a2,unsigned b0,unsigned b1,
                                     float zf){
    asm("mma.sync.aligned.m16n8k16.row.col.f32.bf16.bf16.f32 "
        "{%0,%1,%2,%3},{%4,%5,%6,%7},{%8,%9},{%10,%10,%10,%10};"
        :"=f"(d0),"=f"(d1),"=f"(d2),"=f"(d3)
        :"r"(a0),"r"(0u),"r"(a2),"r"(0u),"r"(b0),"r"(b1),"f"(zf));
}
// D += A*B
__device__ __forceinline__ void mmaA(float&d0,float&d1,float&d2,float&d3,
                                     unsigned a0,unsigned a2,unsigned b0,unsigned b1){
    asm("mma.sync.aligned.m16n8k16.row.col.f32.bf16.bf16.f32 "
        "{%0,%1,%2,%3},{%4,%5,%6,%7},{%8,%9},{%0,%1,%2,%3};"
        :"+f"(d0),"+f"(d1),"+f"(d2),"+f"(d3)
        :"r"(a0),"r"(0u),"r"(a2),"r"(0u),"r"(b0),"r"(b1));
}

// ONE WARP = 8 batch rows via m16n8k16 mma.sync (layout identity validated R13).
// This round: kt-OUTER/nt-INNER mma order (dep distance 8 between chain links),
// zero-C first pass, in-step mask (no early-vote path), no ev copy.
__global__ __launch_bounds__(32, 1) void crf_mma_kernel(
    const float* __restrict__ y_pred,   // [B, N, K]
    const float* __restrict__ trans,    // [K, K]
    const int*   __restrict__ y_true,   // [B, N]
    float*       __restrict__ out,      // [B]
    int N, int B)
{
    const int lane = threadIdx.x & 31;
    const int g    = lane >> 2;
    const int tid  = lane & 3;
    const int rraw = blockIdx.x * 8 + g;
    const int row  = (rraw < B) ? rraw : (B - 1);

    const float* Y  = y_pred + (size_t)row * N * KDIM;
    const int*   Tr = y_true + (size_t)row * N;

    // ---- B fragments: E = exp(trans), tile (kt,nt): col j = 8nt+g ----
    unsigned Bf0[4][8], Bf1[4][8];
#pragma unroll
    for (int kt = 0; kt < 4; ++kt)
#pragma unroll
        for (int nt = 0; nt < 8; ++nt) {
            int c = 8 * nt + g, r0 = 16 * kt + 2 * tid;
            Bf0[kt][nt] = cvt_bf2(__expf(trans[(r0 + 1) * KDIM + c]),
                                  __expf(trans[(r0    ) * KDIM + c]));
            Bf1[kt][nt] = cvt_bf2(__expf(trans[(r0 + 9) * KDIM + c]),
                                  __expf(trans[(r0 + 8) * KDIM + c]));
        }

    // ---- t = 0: state init ----
    float2 e0[8];
#pragma unroll
    for (int nt = 0; nt < 8; ++nt) e0[nt] = *(const float2*)(Y + 8 * nt + 2 * tid);
    float mn0 = fminf(e0[0].x, e0[0].y);
#pragma unroll
    for (int nt = 1; nt < 8; ++nt) mn0 = fminf(mn0, fminf(e0[nt].x, e0[nt].y));
    float fm0 = (grpmin(mn0) > TH) ? 1.0f : 0.0f;

    unsigned a0[4], a2[4];
#pragma unroll
    for (int kt = 0; kt < 4; ++kt) {
        float2 qe = e0[2 * kt], qo = e0[2 * kt + 1];
        a0[kt] = cvt_bf2(ex2f(qe.y * fm0 * LOG2E), ex2f(qe.x * fm0 * LOG2E));
        a2[kt] = cvt_bf2(ex2f(qo.y * fm0 * LOG2E), ex2f(qo.x * fm0 * LOG2E));
    }
    int d = __shfl_sync(FULL, (int)((a0[0] >> 7) & 0xFFu) - 127, lane & ~3);
    int C2i = 0;

    int yt0 = Tr[0];
    float point = Y[yt0] * fm0;
    float tv = 0.0f, fmprev = fm0;

    // ---- prime emit ring: slot = t & 3 ----
    float2 ring[4][8];
#pragma unroll
    for (int p = 1; p <= 4; ++p) {
        int tt = (p < N) ? p : (N - 1);
#pragma unroll
        for (int nt = 0; nt < 8; ++nt)
            ring[p & 3][nt] = *(const float2*)(Y + (size_t)tt * KDIM + 8 * nt + 2 * tid);
    }
    // label pipeline at loop entry T = 1 (verified in R13):
    int ytA = Tr[(1 < N) ? 1 : (N - 1)];
    int ytB = Tr[(2 < N) ? 2 : (N - 1)];
    int ytC = Tr[(3 < N) ? 3 : (N - 1)];
    int ytD = Tr[(4 < N) ? 4 : (N - 1)];
    float pgc = Y[(size_t)((1 < N) ? 1 : (N - 1)) * KDIM + ytA];   // Y[T][yt(T)]
    float pgn = Y[(size_t)((2 < N) ? 2 : (N - 1)) * KDIM + ytB];   // Y[T+1][yt(T+1)]
    float trvc = trans[yt0 * KDIM + ytA];
    float trvn = trans[ytA * KDIM + ytB];

#define STEP(T, S)                                                                   \
    {                                                                                \
        /* p = 2^(emit*lg2e) and mask, from ring slot S (this step's emits) */       \
        float pa[8], pb[8];                                                          \
        _Pragma("unroll")                                                            \
        for (int nt = 0; nt < 8; ++nt) {                                             \
            pa[nt] = ex2f(ring[S][nt].x * LOG2E);                                    \
            pb[nt] = ex2f(ring[S][nt].y * LOG2E);                                    \
        }                                                                            \
        float mn = fminf(ring[S][0].x, ring[S][0].y);                                \
        _Pragma("unroll")                                                            \
        for (int nt = 1; nt < 8; ++nt)                                               \
            mn = fminf(mn, fminf(ring[S][nt].x, ring[S][nt].y));                     \
        /* refill slot S with step T+4 */                                            \
        int tl = ((T) + 4 < N) ? ((T) + 4) : (N - 1);                                \
        _Pragma("unroll")                                                            \
        for (int nt = 0; nt < 8; ++nt)                                               \
            ring[S][nt] = *(const float2*)(Y + (size_t)tl * KDIM + 8 * nt + 2 * tid);\
        unsigned mcur = (grpmin(mn) > TH) && ((T) < N);                              \
        int ytL = Tr[tl];                                                            \
        float pgN = Y[(size_t)(((T) + 2 < N) ? ((T) + 2) : (N - 1)) * KDIM + ytC];   \
        float trN = trans[ytB * KDIM + ytC];                                         \
        /* s = e x E : kt-outer, nt-inner (independent consecutive HMMAs) */         \
        float d0[8], d1[8], d2[8], d3[8];                                            \
        _Pragma("unroll")                                                            \
        for (int nt = 0; nt < 8; ++nt)                                               \
            mma0(d0[nt], d1[nt], d2[nt], d3[nt], a0[0], a2[0],                       \
                 Bf0[0][nt], Bf1[0][nt], 0.0f);                                      \
        _Pragma("unroll")                                                            \
        for (int kt = 1; kt < 4; ++kt)                                               \
            _Pragma("unroll")                                                        \
            for (int nt = 0; nt < 8; ++nt)                                           \
                mmaA(d0[nt], d1[nt], d2[nt], d3[nt], a0[kt], a2[kt],                 \
                     Bf0[kt][nt], Bf1[kt][nt]);                                      \
        /* pack, mask-select, exact renorm (packed bf16x2 exponent subtract) */      \
        unsigned dd2 = (unsigned)(d * 0x00800080);                                   \
        unsigned res[8];                                                             \
        _Pragma("unroll")                                                            \
        for (int nt = 0; nt < 8; ++nt) {                                             \
            unsigned pk = cvt_bf2(d1[nt] * pb[nt], d0[nt] * pa[nt]);                 \
            unsigned old = (nt & 1) ? a2[nt >> 1] : a0[nt >> 1];                     \
            res[nt] = (mcur ? pk : old) - dd2;                                       \
        }                                                                            \
        _Pragma("unroll")                                                            \
        for (int kt = 0; kt < 4; ++kt) { a0[kt] = res[2 * kt]; a2[kt] = res[2 * kt + 1]; } \
        C2i += d;                                                                    \
        d = __shfl_sync(FULL, (int)((a0[0] >> 7) & 0xFFu) - 127, lane & ~3);         \
        float fmc = mcur ? 1.0f : 0.0f;                                              \
        point += pgc * fmc;                                                          \
        tv += trvc * (fmprev * fmc);                                                 \
        fmprev = fmc;                                                                \
        pgc = pgn; pgn = pgN;                                                        \
        trvc = trvn; trvn = trN;                                                     \
        ytA = ytB; ytB = ytC; ytC = ytD; ytD = ytL;                                  \
    }

    // ---- main loop: t0 === 1 (mod 4); steps t >= N run masked (harmless) ----
    for (int t0 = 1; t0 < N; t0 += 4) {
        STEP(t0 + 0, 1)
        STEP(t0 + 1, 2)
        STEP(t0 + 2, 3)
        STEP(t0 + 3, 0)
    }
#undef STEP

    // ---- epilogue ----
    float se = 0.0f;
#pragma unroll
    for (int kt = 0; kt < 4; ++kt)
        se += bflo(a0[kt]) + bfhi(a0[kt]) + bflo(a2[kt]) + bfhi(a2[kt]);
    se += __shfl_xor_sync(FULL, se, 1);
    se += __shfl_xor_sync(FULL, se, 2);
    if (tid == 0 && rraw < B)
        out[rraw] = LN2 * ((float)C2i + lg2f(se)) - (point + tv);
}

extern "C" void kernel_launch(void* const* d_in, const int* in_sizes, int n_in,
                              void* d_out, int out_size) {
    const float* y_pred = (const float*)d_in[0];   // [B, N, K] f32
    const float* trans  = (const float*)d_in[1];   // [K, K]    f32
    const int*   y_true = (const int*)  d_in[2];   // [B, N]    i32
    float* out = (float*)d_out;                    // [B]       f32

    int B = out_size;                  // 512
    int N = in_sizes[2] / B;           // 1024
    int blocks = (B + 7) / 8;          // 64 warps, 8 rows each
    crf_mma_kernel<<<blocks, 32>>>(y_pred, trans, y_true, out, N, B);
}